// round 12
// baseline (speedup 1.0000x reference)
#include <cuda_runtime.h>
#include <cuda_bf16.h>
#include <cstdint>

// DNN_84026740179139: embedding-bag mean + 3x[64x64 Linear+ReLU].
// R12: revert K2 to R10 shape, then refine.
//   K2: tile 4 rows x 8 dims, RPB=64, 128thr, grid 256. W via __ldg (2 cache
//       lines/warp -> cheaper than LDS path), no W smem staging, 1-deep k-prefetch.
//   K1: idx rows staged into PADDED shared (stride 52) -> int4 idx reads
//       (13 LDS/warp instead of 50), 8 gather LDG.128 in flight.

#define BATCH   16384
#define DIMS    64
#define NNZ     50

typedef unsigned long long u64;

__device__ __forceinline__ u64 ffma2(u64 a, u64 b, u64 c) {
    u64 d; asm("fma.rn.f32x2 %0, %1, %2, %3;" : "=l"(d) : "l"(a), "l"(b), "l"(c)); return d;
}
__device__ __forceinline__ u64 add2(u64 a, u64 b) {
    u64 d; asm("add.rn.f32x2 %0, %1, %2;" : "=l"(d) : "l"(a), "l"(b)); return d;
}
__device__ __forceinline__ u64 mul2(u64 a, u64 b) {
    u64 d; asm("mul.rn.f32x2 %0, %1, %2;" : "=l"(d) : "l"(a), "l"(b)); return d;
}
__device__ __forceinline__ u64 pack2(float x, float y) {
    u64 d; asm("mov.b64 %0, {%1, %2};" : "=l"(d) : "f"(x), "f"(y)); return d;
}
__device__ __forceinline__ void unpack2(u64 d, float& x, float& y) {
    asm("mov.b64 {%0, %1}, %2;" : "=f"(x), "=f"(y) : "l"(d));
}

// 4MB scratch for pooled embeddings X[BATCH][DIMS]
__device__ float g_X[BATCH * DIMS];

// ================= K1 : gather + mean =================
#define K1_RPB   16
#define K1_THR   256
#define K1_GRID  (BATCH / K1_RPB)   // 1024
#define IDXS     52                 // padded idx row stride (13 int4)

__global__ __launch_bounds__(K1_THR) void gather_kernel(
    const float* __restrict__ emb,
    const int*   __restrict__ fidx)
{
    __shared__ int sIdx[K1_RPB * IDXS];    // 3.3 KB, padded rows

    const int tid = threadIdx.x;
    // stage 800 contiguous ints into padded layout (row r at r*IDXS)
    {
        const int* src = fidx + blockIdx.x * K1_RPB * NNZ;
        #pragma unroll
        for (int s = 0; s < 4; s++) {
            const int i = tid + s * K1_THR;     // 0..1023
            if (i < K1_RPB * NNZ) {
                const int r = i / NNZ;
                const int j = i - r * NNZ;
                sIdx[r * IDXS + j] = src[i];
            }
        }
    }
    __syncthreads();

    const int warp = tid >> 5;
    const int lane = tid & 31;
    const int half = lane >> 4;
    const int c    = lane & 15;
    const int lrow = 2 * warp + half;

    const ulonglong2* emb2 = (const ulonglong2*)emb;
    const int4* idx4 = (const int4*)(sIdx + lrow * IDXS);   // aligned: IDXS%4==0
    u64 a01 = 0ull, a23 = 0ull;

    // 48 = 12 int4 groups; 8 gather LDG.128 in flight per group
    #pragma unroll 3
    for (int g = 0; g < 12; g++) {
        const int4 id = idx4[g];
        const ulonglong2 v0 = __ldg(&emb2[(size_t)id.x * 16 + c]);
        const ulonglong2 v1 = __ldg(&emb2[(size_t)id.y * 16 + c]);
        const ulonglong2 v2 = __ldg(&emb2[(size_t)id.z * 16 + c]);
        const ulonglong2 v3 = __ldg(&emb2[(size_t)id.w * 16 + c]);
        a01 = add2(a01, v0.x); a23 = add2(a23, v0.y);
        a01 = add2(a01, v1.x); a23 = add2(a23, v1.y);
        a01 = add2(a01, v2.x); a23 = add2(a23, v2.y);
        a01 = add2(a01, v3.x); a23 = add2(a23, v3.y);
    }
    // tail: idx 48, 49
    {
        const int4 id = idx4[12];
        const ulonglong2 v0 = __ldg(&emb2[(size_t)id.x * 16 + c]);
        const ulonglong2 v1 = __ldg(&emb2[(size_t)id.y * 16 + c]);
        a01 = add2(a01, v0.x); a23 = add2(a23, v0.y);
        a01 = add2(a01, v1.x); a23 = add2(a23, v1.y);
    }

    const u64 inv2 = pack2(1.0f / NNZ, 1.0f / NNZ);
    a01 = mul2(a01, inv2);
    a23 = mul2(a23, inv2);

    float f0, f1, f2, f3;
    unpack2(a01, f0, f1);
    unpack2(a23, f2, f3);
    const int grow = blockIdx.x * K1_RPB + lrow;
    *(float4*)(g_X + (size_t)grow * DIMS + 4 * c) = make_float4(f0, f1, f2, f3);
}

// ================= K2 : 3x (Linear + ReLU) =================
#define K2_RPB   64
#define K2_THR   128
#define K2_GRID  (BATCH / K2_RPB)   // 256
#define XTS      68                 // sXt row stride (mult of 4 -> 16B-aligned)

__global__ __launch_bounds__(K2_THR) void mlp_kernel(
    const float* __restrict__ W0, const float* __restrict__ b0,
    const float* __restrict__ W1, const float* __restrict__ b1,
    const float* __restrict__ b2, const float* __restrict__ W2,
    float* __restrict__ out)
{
    __shared__ float sXt[DIMS * XTS];      // 17.4 KB x transposed: sXt[k*XTS + r]

    const int tid = threadIdx.x;

    // ---- load X tile [64 rows x 64] (coalesced) + transpose into sXt ----
    {
        const float4* X4 = (const float4*)(g_X + (size_t)blockIdx.x * K2_RPB * DIMS);
        #pragma unroll
        for (int s = 0; s < 8; s++) {
            const int idx = tid + s * K2_THR;       // 0..1023
            const int row = idx >> 4;               // 0..63
            const int cg  = idx & 15;               // dims 4cg..4cg+3
            const float4 v = X4[idx];
            sXt[(4 * cg + 0) * XTS + row] = v.x;
            sXt[(4 * cg + 1) * XTS + row] = v.y;
            sXt[(4 * cg + 2) * XTS + row] = v.z;
            sXt[(4 * cg + 3) * XTS + row] = v.w;
        }
    }
    __syncthreads();

    // ---- GEMM: thread tile = 4 rows (2 packed pairs) x 8 dims ----
    const int r0 = 4 * (tid & 15);
    const int d0 = 8 * (tid >> 4);

    const float* Wn[3] = {W0, W1, W2};
    const float* bn[3] = {b0, b1, b2};

    u64 y2[2][8];   // y2[p][dd] = (y[r0+2p][d0+dd], y[r0+2p+1][d0+dd])

    #pragma unroll
    for (int l = 0; l < 3; l++) {
        const float* Wl = Wn[l];
        {
            const float4 ba = __ldg((const float4*)(bn[l]) + (d0 >> 2));
            const float4 bb = __ldg((const float4*)(bn[l]) + (d0 >> 2) + 1);
            y2[0][0] = pack2(ba.x, ba.x); y2[0][1] = pack2(ba.y, ba.y);
            y2[0][2] = pack2(ba.z, ba.z); y2[0][3] = pack2(ba.w, ba.w);
            y2[0][4] = pack2(bb.x, bb.x); y2[0][5] = pack2(bb.y, bb.y);
            y2[0][6] = pack2(bb.z, bb.z); y2[0][7] = pack2(bb.w, bb.w);
            #pragma unroll
            for (int dd = 0; dd < 8; dd++) y2[1][dd] = y2[0][dd];
        }

        // ---- software-pipelined k-loop; W straight from gmem (L1-resident) ----
        ulonglong2 xv = *(const ulonglong2*)(sXt + r0);
        float4 wa = __ldg((const float4*)(Wl + d0));
        float4 wb = __ldg((const float4*)(Wl + d0 + 4));

        #pragma unroll 4
        for (int k = 0; k < DIMS; k++) {
            ulonglong2 xn;
            float4 wan, wbn;
            if (k < DIMS - 1) {
                xn  = *(const ulonglong2*)(sXt + (k + 1) * XTS + r0);
                wan = __ldg((const float4*)(Wl + (k + 1) * DIMS + d0));
                wbn = __ldg((const float4*)(Wl + (k + 1) * DIMS + d0 + 4));
            }

            u64 w2[8];
            w2[0] = pack2(wa.x, wa.x); w2[1] = pack2(wa.y, wa.y);
            w2[2] = pack2(wa.z, wa.z); w2[3] = pack2(wa.w, wa.w);
            w2[4] = pack2(wb.x, wb.x); w2[5] = pack2(wb.y, wb.y);
            w2[6] = pack2(wb.z, wb.z); w2[7] = pack2(wb.w, wb.w);
            #pragma unroll
            for (int dd = 0; dd < 8; dd++) {
                y2[0][dd] = ffma2(xv.x, w2[dd], y2[0][dd]);
                y2[1][dd] = ffma2(xv.y, w2[dd], y2[1][dd]);
            }

            xv = xn; wa = wan; wb = wbn;
        }

        // ReLU
        #pragma unroll
        for (int p = 0; p < 2; p++)
            #pragma unroll
            for (int dd = 0; dd < 8; dd++) {
                float a, b;
                unpack2(y2[p][dd], a, b);
                y2[p][dd] = pack2(fmaxf(a, 0.f), fmaxf(b, 0.f));
            }

        if (l < 2) {
            __syncthreads();     // all reads of sXt(l) done
            #pragma unroll
            for (int p = 0; p < 2; p++)
                #pragma unroll
                for (int dd = 0; dd < 8; dd++)
                    *(u64*)(sXt + (d0 + dd) * XTS + r0 + 2 * p) = y2[p][dd];
            __syncthreads();     // next layer's x visible
        }
    }

    // ---- store out[B,64]: 4 rows x 8 dims = 8 STG.128 ----
    #pragma unroll
    for (int p = 0; p < 2; p++) {
        float lo[8], hi[8];
        #pragma unroll
        for (int dd = 0; dd < 8; dd++) unpack2(y2[p][dd], lo[dd], hi[dd]);
        const size_t gr = (size_t)blockIdx.x * K2_RPB + r0 + 2 * p;
        *(float4*)(out + gr * DIMS + d0)           = make_float4(lo[0], lo[1], lo[2], lo[3]);
        *(float4*)(out + gr * DIMS + d0 + 4)       = make_float4(lo[4], lo[5], lo[6], lo[7]);
        *(float4*)(out + (gr + 1) * DIMS + d0)     = make_float4(hi[0], hi[1], hi[2], hi[3]);
        *(float4*)(out + (gr + 1) * DIMS + d0 + 4) = make_float4(hi[4], hi[5], hi[6], hi[7]);
    }
}

extern "C" void kernel_launch(void* const* d_in, const int* in_sizes, int n_in,
                              void* d_out, int out_size)
{
    // Resolve inputs by element count:
    //   emb_table 6400000 f32; feature_indices 819200 i32 (first occurrence);
    //   W* 4096 f32 in order; b* 64 f32 in order.
    const float* emb  = nullptr;
    const int*   fidx = nullptr;
    const float* W[3] = {nullptr, nullptr, nullptr};
    const float* b[3] = {nullptr, nullptr, nullptr};
    int wi = 0, bi = 0;

    for (int i = 0; i < n_in; i++) {
        const int sz = in_sizes[i];
        if (sz == 100000 * 64) {
            emb = (const float*)d_in[i];
        } else if (sz == BATCH * NNZ) {
            if (!fidx) fidx = (const int*)d_in[i];
        } else if (sz == DIMS * DIMS) {
            if (wi < 3) W[wi++] = (const float*)d_in[i];
        } else if (sz == DIMS) {
            if (bi < 3) b[bi++] = (const float*)d_in[i];
        }
    }

    float* out = (float*)d_out;
    gather_kernel<<<K1_GRID, K1_THR>>>(emb, fidx);
    mlp_kernel<<<K2_GRID, K2_THR>>>(W[0], b[0], W[1], b[1], b[2], W[2], out);
}

// round 13
// speedup vs baseline: 1.3024x; 1.3024x over previous
#include <cuda_runtime.h>
#include <cuda_bf16.h>
#include <cstdint>

// DNN_84026740179139: embedding-bag mean + 3x[64x64 Linear+ReLU].
// R13: best measured components only.
//   K2 = EXACT R10 kernel (17.4us measured): tile 4rows x 8dims, W staged scalar
//        in shared (LDG-W experiments R11/R12 falsified: ~45us), no sw pipeline.
//   K1 = R12 variant: padded sIdx rows -> int4 idx reads (13 LDS vs 50), 8
//        gather LDG.128 in flight.

#define BATCH   16384
#define DIMS    64
#define NNZ     50

typedef unsigned long long u64;

__device__ __forceinline__ u64 ffma2(u64 a, u64 b, u64 c) {
    u64 d; asm("fma.rn.f32x2 %0, %1, %2, %3;" : "=l"(d) : "l"(a), "l"(b), "l"(c)); return d;
}
__device__ __forceinline__ u64 add2(u64 a, u64 b) {
    u64 d; asm("add.rn.f32x2 %0, %1, %2;" : "=l"(d) : "l"(a), "l"(b)); return d;
}
__device__ __forceinline__ u64 mul2(u64 a, u64 b) {
    u64 d; asm("mul.rn.f32x2 %0, %1, %2;" : "=l"(d) : "l"(a), "l"(b)); return d;
}
__device__ __forceinline__ u64 pack2(float x, float y) {
    u64 d; asm("mov.b64 %0, {%1, %2};" : "=l"(d) : "f"(x), "f"(y)); return d;
}
__device__ __forceinline__ void unpack2(u64 d, float& x, float& y) {
    asm("mov.b64 {%0, %1}, %2;" : "=f"(x), "=f"(y) : "l"(d));
}

// 4MB scratch for pooled embeddings X[BATCH][DIMS]
__device__ float g_X[BATCH * DIMS];

// ================= K1 : gather + mean (R12 int4-idx) =================
#define K1_RPB   16
#define K1_THR   256
#define K1_GRID  (BATCH / K1_RPB)   // 1024
#define IDXS     52                 // padded idx row stride (13 int4)

__global__ __launch_bounds__(K1_THR) void gather_kernel(
    const float* __restrict__ emb,
    const int*   __restrict__ fidx)
{
    __shared__ int sIdx[K1_RPB * IDXS];    // 3.3 KB, padded rows

    const int tid = threadIdx.x;
    {
        const int* src = fidx + blockIdx.x * K1_RPB * NNZ;
        #pragma unroll
        for (int s = 0; s < 4; s++) {
            const int i = tid + s * K1_THR;     // 0..1023
            if (i < K1_RPB * NNZ) {
                const int r = i / NNZ;
                const int j = i - r * NNZ;
                sIdx[r * IDXS + j] = src[i];
            }
        }
    }
    __syncthreads();

    const int warp = tid >> 5;
    const int lane = tid & 31;
    const int half = lane >> 4;
    const int c    = lane & 15;
    const int lrow = 2 * warp + half;

    const ulonglong2* emb2 = (const ulonglong2*)emb;
    const int4* idx4 = (const int4*)(sIdx + lrow * IDXS);
    u64 a01 = 0ull, a23 = 0ull;

    #pragma unroll 3
    for (int g = 0; g < 12; g++) {
        const int4 id = idx4[g];
        const ulonglong2 v0 = __ldg(&emb2[(size_t)id.x * 16 + c]);
        const ulonglong2 v1 = __ldg(&emb2[(size_t)id.y * 16 + c]);
        const ulonglong2 v2 = __ldg(&emb2[(size_t)id.z * 16 + c]);
        const ulonglong2 v3 = __ldg(&emb2[(size_t)id.w * 16 + c]);
        a01 = add2(a01, v0.x); a23 = add2(a23, v0.y);
        a01 = add2(a01, v1.x); a23 = add2(a23, v1.y);
        a01 = add2(a01, v2.x); a23 = add2(a23, v2.y);
        a01 = add2(a01, v3.x); a23 = add2(a23, v3.y);
    }
    {
        const int4 id = idx4[12];
        const ulonglong2 v0 = __ldg(&emb2[(size_t)id.x * 16 + c]);
        const ulonglong2 v1 = __ldg(&emb2[(size_t)id.y * 16 + c]);
        a01 = add2(a01, v0.x); a23 = add2(a23, v0.y);
        a01 = add2(a01, v1.x); a23 = add2(a23, v1.y);
    }

    const u64 inv2 = pack2(1.0f / NNZ, 1.0f / NNZ);
    a01 = mul2(a01, inv2);
    a23 = mul2(a23, inv2);

    float f0, f1, f2, f3;
    unpack2(a01, f0, f1);
    unpack2(a23, f2, f3);
    const int grow = blockIdx.x * K1_RPB + lrow;
    *(float4*)(g_X + (size_t)grow * DIMS + 4 * c) = make_float4(f0, f1, f2, f3);
}

// ================= K2 : 3x (Linear + ReLU) — EXACT R10 =================
#define K2_RPB   64
#define K2_THR   128
#define K2_GRID  (BATCH / K2_RPB)   // 256
#define XTS      68                 // sXt row stride (mult of 4 -> 16B-aligned)

__global__ __launch_bounds__(K2_THR) void mlp_kernel(
    const float* __restrict__ W0, const float* __restrict__ b0,
    const float* __restrict__ W1, const float* __restrict__ b1,
    const float* __restrict__ b2, const float* __restrict__ W2,
    float* __restrict__ out)
{
    __shared__ float sW[DIMS * DIMS];      // 16 KB scalar weights
    __shared__ float sXt[DIMS * XTS];      // 17.4 KB x transposed

    const int tid = threadIdx.x;

    // ---- stage W0 ----
    {
        const float4* src = (const float4*)W0;
        float4*       dst = (float4*)sW;
        #pragma unroll
        for (int s = 0; s < 8; s++)
            dst[tid + s * K2_THR] = src[tid + s * K2_THR];
    }

    // ---- load X tile [64 rows x 64] + transpose into sXt ----
    {
        const float4* X4 = (const float4*)(g_X + (size_t)blockIdx.x * K2_RPB * DIMS);
        #pragma unroll
        for (int s = 0; s < 8; s++) {
            const int idx = tid + s * K2_THR;       // 0..1023
            const int row = idx >> 4;               // 0..63
            const int cg  = idx & 15;               // dims 4cg..4cg+3
            const float4 v = X4[idx];
            sXt[(4 * cg + 0) * XTS + row] = v.x;
            sXt[(4 * cg + 1) * XTS + row] = v.y;
            sXt[(4 * cg + 2) * XTS + row] = v.z;
            sXt[(4 * cg + 3) * XTS + row] = v.w;
        }
    }
    __syncthreads();

    // ---- GEMM: thread tile = 4 rows (2 packed pairs) x 8 dims ----
    const int r0 = 4 * (tid & 15);
    const int d0 = 8 * (tid >> 4);

    const float* Wn[3] = {W0, W1, W2};
    const float* bn[3] = {b0, b1, b2};

    u64 y2[2][8];

    #pragma unroll
    for (int l = 0; l < 3; l++) {
        {
            const float4 ba = __ldg((const float4*)(bn[l]) + (d0 >> 2));
            const float4 bb = __ldg((const float4*)(bn[l]) + (d0 >> 2) + 1);
            y2[0][0] = pack2(ba.x, ba.x); y2[0][1] = pack2(ba.y, ba.y);
            y2[0][2] = pack2(ba.z, ba.z); y2[0][3] = pack2(ba.w, ba.w);
            y2[0][4] = pack2(bb.x, bb.x); y2[0][5] = pack2(bb.y, bb.y);
            y2[0][6] = pack2(bb.z, bb.z); y2[0][7] = pack2(bb.w, bb.w);
            #pragma unroll
            for (int dd = 0; dd < 8; dd++) y2[1][dd] = y2[0][dd];
        }

        #pragma unroll 8
        for (int k = 0; k < DIMS; k++) {
            const ulonglong2 xv = *(const ulonglong2*)(sXt + k * XTS + r0);
            const float4 wa = *(const float4*)(sW + k * DIMS + d0);
            const float4 wb = *(const float4*)(sW + k * DIMS + d0 + 4);
            u64 w2[8];
            w2[0] = pack2(wa.x, wa.x); w2[1] = pack2(wa.y, wa.y);
            w2[2] = pack2(wa.z, wa.z); w2[3] = pack2(wa.w, wa.w);
            w2[4] = pack2(wb.x, wb.x); w2[5] = pack2(wb.y, wb.y);
            w2[6] = pack2(wb.z, wb.z); w2[7] = pack2(wb.w, wb.w);
            #pragma unroll
            for (int dd = 0; dd < 8; dd++) {
                y2[0][dd] = ffma2(xv.x, w2[dd], y2[0][dd]);
                y2[1][dd] = ffma2(xv.y, w2[dd], y2[1][dd]);
            }
        }

        // ReLU
        #pragma unroll
        for (int p = 0; p < 2; p++)
            #pragma unroll
            for (int dd = 0; dd < 8; dd++) {
                float a, b;
                unpack2(y2[p][dd], a, b);
                y2[p][dd] = pack2(fmaxf(a, 0.f), fmaxf(b, 0.f));
            }

        if (l < 2) {
            __syncthreads();
            {
                const float4* src = (const float4*)Wn[l + 1];
                float4*       dst = (float4*)sW;
                #pragma unroll
                for (int s = 0; s < 8; s++)
                    dst[tid + s * K2_THR] = src[tid + s * K2_THR];
            }
            #pragma unroll
            for (int p = 0; p < 2; p++)
                #pragma unroll
                for (int dd = 0; dd < 8; dd++)
                    *(u64*)(sXt + (d0 + dd) * XTS + r0 + 2 * p) = y2[p][dd];
            __syncthreads();
        }
    }

    // ---- store out[B,64]: 4 rows x 8 dims = 8 STG.128 ----
    #pragma unroll
    for (int p = 0; p < 2; p++) {
        float lo[8], hi[8];
        #pragma unroll
        for (int dd = 0; dd < 8; dd++) unpack2(y2[p][dd], lo[dd], hi[dd]);
        const size_t gr = (size_t)blockIdx.x * K2_RPB + r0 + 2 * p;
        *(float4*)(out + gr * DIMS + d0)           = make_float4(lo[0], lo[1], lo[2], lo[3]);
        *(float4*)(out + gr * DIMS + d0 + 4)       = make_float4(lo[4], lo[5], lo[6], lo[7]);
        *(float4*)(out + (gr + 1) * DIMS + d0)     = make_float4(hi[0], hi[1], hi[2], hi[3]);
        *(float4*)(out + (gr + 1) * DIMS + d0 + 4) = make_float4(hi[4], hi[5], hi[6], hi[7]);
    }
}

extern "C" void kernel_launch(void* const* d_in, const int* in_sizes, int n_in,
                              void* d_out, int out_size)
{
    // Resolve inputs by element count:
    //   emb_table 6400000 f32; feature_indices 819200 i32 (first occurrence);
    //   W* 4096 f32 in order; b* 64 f32 in order.
    const float* emb  = nullptr;
    const int*   fidx = nullptr;
    const float* W[3] = {nullptr, nullptr, nullptr};
    const float* b[3] = {nullptr, nullptr, nullptr};
    int wi = 0, bi = 0;

    for (int i = 0; i < n_in; i++) {
        const int sz = in_sizes[i];
        if (sz == 100000 * 64) {
            emb = (const float*)d_in[i];
        } else if (sz == BATCH * NNZ) {
            if (!fidx) fidx = (const int*)d_in[i];
        } else if (sz == DIMS * DIMS) {
            if (wi < 3) W[wi++] = (const float*)d_in[i];
        } else if (sz == DIMS) {
            if (bi < 3) b[bi++] = (const float*)d_in[i];
        }
    }

    float* out = (float*)d_out;
    gather_kernel<<<K1_GRID, K1_THR>>>(emb, fidx);
    mlp_kernel<<<K2_GRID, K2_THR>>>(W[0], b[0], W[1], b[1], b[2], W[2], out);
}